// round 12
// baseline (speedup 1.0000x reference)
#include <cuda_runtime.h>
#include <cuda_bf16.h>
#include <cstdint>

// DistMult edge scoring:
//   out[r, e] = sigmoid( sum_d h[src[r,e], d] * W[r, d] * h[dst[r,e], d] )
// h [100000,128] f32, W [6,128] f32, src/dst [6,200000] int32, out [6,200000] f32.
//
// R12: persistent-ish grid. R11 (64us) had occ=91%, L2=76%, L1=72% with
// 12.7 waves of CTAs: wave transitions + per-wave prologue re-execution
// cost ~6-9%. GRID_X 2500->500, ITERS 5->25 (3000 CTAs ~ 2.5 waves),
// index preload grows to 400 int2 (3.2KB smem). Same 16-lane f32x2 body
// (regs=32, packed mul/fma halves fp issue).

#define N_HID 128
#define E_PER_REL 200000
#define N_REL 6
#define BLOCK 256
#define EDGES_PER_BLOCK 16      // 256 threads / 16 lanes per edge
#define GRID_X 500              // 500 * 16 * 25 == 200000 exactly
#define ITERS 25
#define STRIDE (GRID_X * EDGES_PER_BLOCK)   // 8000
#define ROW_U2 (N_HID / 4)      // 32 ulonglong2 per 128-float row

__device__ __forceinline__ unsigned long long f32x2_mul(unsigned long long a,
                                                        unsigned long long b) {
    unsigned long long r;
    asm("mul.rn.f32x2 %0, %1, %2;" : "=l"(r) : "l"(a), "l"(b));
    return r;
}
__device__ __forceinline__ unsigned long long f32x2_fma(unsigned long long a,
                                                        unsigned long long b,
                                                        unsigned long long c) {
    unsigned long long r;
    asm("fma.rn.f32x2 %0, %1, %2, %3;" : "=l"(r) : "l"(a), "l"(b), "l"(c));
    return r;
}

__global__ __launch_bounds__(BLOCK, 6)
void distmult_kernel(const ulonglong2* __restrict__ h8,   // row = 32 x ulonglong2
                     const ulonglong2* __restrict__ W8,
                     const int* __restrict__ src_idx,
                     const int* __restrict__ dst_idx,
                     float* __restrict__ out) {
    __shared__ int2 SD[ITERS * EDGES_PER_BLOCK];   // 400 pairs, 3.2 KB

    const int rel   = blockIdx.y;
    const int tid   = threadIdx.x;
    const int sub   = tid & 15;    // lane within 16-lane edge group
    const int group = tid >> 4;    // edge slot within block: 0..15

    const int* __restrict__ srcR = src_idx + rel * E_PER_REL;
    const int* __restrict__ dstR = dst_idx + rel * E_PER_REL;
    float* __restrict__ outR = out + rel * E_PER_REL;

    // W row in registers: lane sub owns ulonglong2 chunks {sub, sub+16} of 32.
    const ulonglong2 w0 = W8[rel * ROW_U2 + sub];
    const ulonglong2 w1 = W8[rel * ROW_U2 + sub + 16];

    // Prologue: preload ALL 25 phases' (s,d) pairs, coalesced (2 rounds).
    for (int t = tid; t < ITERS * EDGES_PER_BLOCK; t += BLOCK) {
        const int i = t >> 4;            // phase
        const int g = t & 15;            // group slot
        const int e = blockIdx.x * EDGES_PER_BLOCK + i * STRIDE + g;
        SD[t] = make_int2(__ldg(srcR + e), __ldg(dstR + e));
    }
    __syncthreads();

    const int e0 = blockIdx.x * EDGES_PER_BLOCK + group;

    #pragma unroll 5
    for (int i = 0; i < ITERS; i++) {
        const int2 sd = SD[i * EDGES_PER_BLOCK + group];   // one LDS.64, broadcast

        const ulonglong2* __restrict__ hs = h8 + (long long)sd.x * ROW_U2;
        const ulonglong2* __restrict__ hd = h8 + (long long)sd.y * ROW_U2;

        // 4 independent LDG.128 per thread, front-batched.
        ulonglong2 a0 = hs[sub];
        ulonglong2 a1 = hs[sub + 16];
        ulonglong2 b0 = hd[sub];
        ulonglong2 b1 = hd[sub + 16];

        // Packed math: 8 f32x2 ops cover this thread's 8 dims.
        unsigned long long acc2;
        acc2 = f32x2_mul(f32x2_mul(a0.x, b0.x), w0.x);
        acc2 = f32x2_fma(f32x2_mul(a0.y, b0.y), w0.y, acc2);
        acc2 = f32x2_fma(f32x2_mul(a1.x, b1.x), w1.x, acc2);
        acc2 = f32x2_fma(f32x2_mul(a1.y, b1.y), w1.y, acc2);

        // Fold the two packed halves.
        float lo = __uint_as_float((unsigned)(acc2 & 0xFFFFFFFFull));
        float hi = __uint_as_float((unsigned)(acc2 >> 32));
        float acc = lo + hi;

        // Reduce across the 16-lane group.
        acc += __shfl_xor_sync(0xFFFFFFFFu, acc, 8);
        acc += __shfl_xor_sync(0xFFFFFFFFu, acc, 4);
        acc += __shfl_xor_sync(0xFFFFFFFFu, acc, 2);
        acc += __shfl_xor_sync(0xFFFFFFFFu, acc, 1);

        if (sub == 0)
            outR[e0 + i * STRIDE] = 1.0f / (1.0f + __expf(-acc));
    }
}

extern "C" void kernel_launch(void* const* d_in, const int* in_sizes, int n_in,
                              void* d_out, int out_size) {
    const ulonglong2* h8 = (const ulonglong2*)d_in[0];
    const ulonglong2* W8 = (const ulonglong2*)d_in[1];
    const int* src = (const int*)d_in[2];
    const int* dst = (const int*)d_in[3];
    float* out = (float*)d_out;

    dim3 grid(GRID_X, N_REL);
    distmult_kernel<<<grid, BLOCK>>>(h8, W8, src, dst, out);
}

// round 13
// speedup vs baseline: 1.0487x; 1.0487x over previous
#include <cuda_runtime.h>
#include <cuda_bf16.h>
#include <cstdint>

// DistMult edge scoring:
//   out[r, e] = sigmoid( sum_d h[src[r,e], d] * W[r, d] * h[dst[r,e], d] )
// h [100000,128] f32, W [6,128] f32, src/dst [6,200000] int32, out [6,200000] f32.
//
// R13: R11 body (16 lanes/edge, packed f32x2, regs=32, occ=91%) with
// halved wave count: GRID_X 2500->1250, ITERS 5->10 fully unrolled,
// 7500 CTAs = 6.3 waves (was 12.7). __launch_bounds__(256,8) FORCES the
// 32-reg cap so the R12 failure (regs 40 -> 6 CTAs -> occ 68%) cannot
// recur. Index pairs for all 10 phases preloaded to smem (1.28 KB).

#define N_HID 128
#define E_PER_REL 200000
#define N_REL 6
#define BLOCK 256
#define EDGES_PER_BLOCK 16      // 256 threads / 16 lanes per edge
#define GRID_X 1250             // 1250 * 16 * 10 == 200000 exactly
#define ITERS 10
#define STRIDE (GRID_X * EDGES_PER_BLOCK)   // 20000
#define ROW_U2 (N_HID / 4)      // 32 ulonglong2 per 128-float row

__device__ __forceinline__ unsigned long long f32x2_mul(unsigned long long a,
                                                        unsigned long long b) {
    unsigned long long r;
    asm("mul.rn.f32x2 %0, %1, %2;" : "=l"(r) : "l"(a), "l"(b));
    return r;
}
__device__ __forceinline__ unsigned long long f32x2_fma(unsigned long long a,
                                                        unsigned long long b,
                                                        unsigned long long c) {
    unsigned long long r;
    asm("fma.rn.f32x2 %0, %1, %2, %3;" : "=l"(r) : "l"(a), "l"(b), "l"(c));
    return r;
}

__global__ __launch_bounds__(BLOCK, 8)
void distmult_kernel(const ulonglong2* __restrict__ h8,   // row = 32 x ulonglong2
                     const ulonglong2* __restrict__ W8,
                     const int* __restrict__ src_idx,
                     const int* __restrict__ dst_idx,
                     float* __restrict__ out) {
    __shared__ int2 SD[ITERS * EDGES_PER_BLOCK];   // 160 pairs, 1.28 KB

    const int rel   = blockIdx.y;
    const int tid   = threadIdx.x;
    const int sub   = tid & 15;    // lane within 16-lane edge group
    const int group = tid >> 4;    // edge slot within block: 0..15

    const int* __restrict__ srcR = src_idx + rel * E_PER_REL;
    const int* __restrict__ dstR = dst_idx + rel * E_PER_REL;
    float* __restrict__ outR = out + rel * E_PER_REL;

    // W row in registers: lane sub owns ulonglong2 chunks {sub, sub+16} of 32.
    const ulonglong2 w0 = W8[rel * ROW_U2 + sub];
    const ulonglong2 w1 = W8[rel * ROW_U2 + sub + 16];

    // Prologue: preload all 10 phases' (s,d) pairs, coalesced (160 <= 256).
    if (tid < ITERS * EDGES_PER_BLOCK) {
        const int i = tid >> 4;          // phase
        const int g = tid & 15;          // group slot
        const int e = blockIdx.x * EDGES_PER_BLOCK + i * STRIDE + g;
        SD[tid] = make_int2(__ldg(srcR + e), __ldg(dstR + e));
    }
    __syncthreads();

    const int e0 = blockIdx.x * EDGES_PER_BLOCK + group;

    #pragma unroll
    for (int i = 0; i < ITERS; i++) {
        const int2 sd = SD[i * EDGES_PER_BLOCK + group];   // one LDS.64, broadcast

        const ulonglong2* __restrict__ hs = h8 + (long long)sd.x * ROW_U2;
        const ulonglong2* __restrict__ hd = h8 + (long long)sd.y * ROW_U2;

        // 4 independent LDG.128 per thread, front-batched.
        ulonglong2 a0 = hs[sub];
        ulonglong2 a1 = hs[sub + 16];
        ulonglong2 b0 = hd[sub];
        ulonglong2 b1 = hd[sub + 16];

        // Packed math: 8 f32x2 ops cover this thread's 8 dims.
        unsigned long long acc2;
        acc2 = f32x2_mul(f32x2_mul(a0.x, b0.x), w0.x);
        acc2 = f32x2_fma(f32x2_mul(a0.y, b0.y), w0.y, acc2);
        acc2 = f32x2_fma(f32x2_mul(a1.x, b1.x), w1.x, acc2);
        acc2 = f32x2_fma(f32x2_mul(a1.y, b1.y), w1.y, acc2);

        // Fold the two packed halves.
        float lo = __uint_as_float((unsigned)(acc2 & 0xFFFFFFFFull));
        float hi = __uint_as_float((unsigned)(acc2 >> 32));
        float acc = lo + hi;

        // Reduce across the 16-lane group.
        acc += __shfl_xor_sync(0xFFFFFFFFu, acc, 8);
        acc += __shfl_xor_sync(0xFFFFFFFFu, acc, 4);
        acc += __shfl_xor_sync(0xFFFFFFFFu, acc, 2);
        acc += __shfl_xor_sync(0xFFFFFFFFu, acc, 1);

        if (sub == 0)
            outR[e0 + i * STRIDE] = 1.0f / (1.0f + __expf(-acc));
    }
}

extern "C" void kernel_launch(void* const* d_in, const int* in_sizes, int n_in,
                              void* d_out, int out_size) {
    const ulonglong2* h8 = (const ulonglong2*)d_in[0];
    const ulonglong2* W8 = (const ulonglong2*)d_in[1];
    const int* src = (const int*)d_in[2];
    const int* dst = (const int*)d_in[3];
    float* out = (float*)d_out;

    dim3 grid(GRID_X, N_REL);
    distmult_kernel<<<grid, BLOCK>>>(h8, W8, src, dst, out);
}